// round 12
// baseline (speedup 1.0000x reference)
#include <cuda_runtime.h>
#include <cuda_fp16.h>
#include <cstdint>

typedef uint32_t u32;

// smem regions (bytes): fp16 [64x64] tiles, rows 128B, XOR-swizzled 16B granules.
// Qh only (Q residual dropped: 2-pass QK). 40KB total -> 5 CTAs/SM.
#define R_QH 0
#define R_KH 8192
#define R_KL 16384
#define R_VH 24576
#define R_VL 32768
#define SMEM_BYTES 40960
// O staging (f32, stride 68 floats, 17408B) overlays QH/KH/KL after PV.

__device__ __forceinline__ u32 smem_u32(const void* p) {
    u32 a;
    asm("{ .reg .u64 t; cvta.to.shared.u64 t, %1; cvt.u32.u64 %0, t; }" : "=r"(a) : "l"(p));
    return a;
}
__device__ __forceinline__ u32 packh(float f0, float f1) {    // lo half=f0, hi half=f1
    u32 r;
    asm("cvt.rn.f16x2.f32 %0, %1, %2;" : "=r"(r) : "f"(f1), "f"(f0));
    return r;
}
__device__ __forceinline__ u32 packl(u32 h, float f0, float f1) {
    __half2 hh = *reinterpret_cast<__half2*>(&h);
    float2 hf = __half22float2(hh);               // .x = low, .y = high
    return packh(f0 - hf.x, f1 - hf.y);
}
__device__ __forceinline__ void ldsm4(u32* r, u32 addr) {
    asm volatile("ldmatrix.sync.aligned.m8n8.x4.shared.b16 {%0,%1,%2,%3}, [%4];"
        : "=r"(r[0]), "=r"(r[1]), "=r"(r[2]), "=r"(r[3]) : "r"(addr));
}
__device__ __forceinline__ void ldsm4t(u32* r, u32 addr) {
    asm volatile("ldmatrix.sync.aligned.m8n8.x4.trans.shared.b16 {%0,%1,%2,%3}, [%4];"
        : "=r"(r[0]), "=r"(r[1]), "=r"(r[2]), "=r"(r[3]) : "r"(addr));
}
__device__ __forceinline__ void mma16816(float* c, const u32* a, const u32* b) {
    asm volatile(
        "mma.sync.aligned.m16n8k16.row.col.f32.f16.f16.f32 "
        "{%0,%1,%2,%3}, {%4,%5,%6,%7}, {%8,%9}, {%0,%1,%2,%3};"
        : "+f"(c[0]), "+f"(c[1]), "+f"(c[2]), "+f"(c[3])
        : "r"(a[0]), "r"(a[1]), "r"(a[2]), "r"(a[3]), "r"(b[0]), "r"(b[1]));
}

__global__ void __launch_bounds__(64, 5)
attn64_f16x2p(const float* __restrict__ qg_, const float* __restrict__ kg_,
              const float* __restrict__ vg_, const int* __restrict__ mg_,
              float* __restrict__ og_)
{
    extern __shared__ char smem[];
    const u32 sbase = smem_u32(smem);
    const int tid  = threadIdx.x;                 // 0..63
    const int lane = tid & 31;
    const int ww   = tid >> 5;                    // warp 0/1 -> rows 32*ww..32*ww+31

    const int pg = blockIdx.x;                    // one 64x64x64 problem per CTA
    const float* qg = qg_ + (size_t)pg * 4096;
    const float* kg = kg_ + (size_t)pg * 4096;
    const float* vg = vg_ + (size_t)pg * 4096;
    const int*   mg = mg_ + (size_t)(pg >> 9) * 4096;
    float*       og = og_ + (size_t)pg * 4096;

    // ---- Stage: fp32 -> fp16 hi (+ lo for K,V), swizzled granule^(row&7) ----
    // 512 granules per tensor, 64 threads -> 8 iterations.
    #pragma unroll
    for (int it = 0; it < 8; it++) {
        int idx = tid + (it << 6);                // 0..511
        int e = idx << 3;                         // 8 source floats
        int r = idx >> 3;                         // row 0..63
        int h = idx & 7;                          // granule 0..7
        int off = (r << 7) + ((h ^ (r & 7)) << 4);
        float4 f0, f1;
        uint4 hq, lq;

        f0 = *reinterpret_cast<const float4*>(qg + e);
        f1 = *reinterpret_cast<const float4*>(qg + e + 4);
        hq.x = packh(f0.x, f0.y); hq.y = packh(f0.z, f0.w);
        hq.z = packh(f1.x, f1.y); hq.w = packh(f1.z, f1.w);
        *reinterpret_cast<uint4*>(smem + R_QH + off) = hq;   // Q residual dropped

        f0 = *reinterpret_cast<const float4*>(kg + e);
        f1 = *reinterpret_cast<const float4*>(kg + e + 4);
        hq.x = packh(f0.x, f0.y); hq.y = packh(f0.z, f0.w);
        hq.z = packh(f1.x, f1.y); hq.w = packh(f1.z, f1.w);
        lq.x = packl(hq.x, f0.x, f0.y); lq.y = packl(hq.y, f0.z, f0.w);
        lq.z = packl(hq.z, f1.x, f1.y); lq.w = packl(hq.w, f1.z, f1.w);
        *reinterpret_cast<uint4*>(smem + R_KH + off) = hq;
        *reinterpret_cast<uint4*>(smem + R_KL + off) = lq;

        f0 = *reinterpret_cast<const float4*>(vg + e);
        f1 = *reinterpret_cast<const float4*>(vg + e + 4);
        hq.x = packh(f0.x, f0.y); hq.y = packh(f0.z, f0.w);
        hq.z = packh(f1.x, f1.y); hq.w = packh(f1.z, f1.w);
        lq.x = packl(hq.x, f0.x, f0.y); lq.y = packl(hq.y, f0.z, f0.w);
        lq.z = packl(hq.z, f1.x, f1.y); lq.w = packl(hq.w, f1.z, f1.w);
        *reinterpret_cast<uint4*>(smem + R_VH + off) = hq;
        *reinterpret_cast<uint4*>(smem + R_VL + off) = lq;
    }
    __syncthreads();

    // ---- ldmatrix address templates (validated in rounds 9/10) ----
    const int sw      = lane & 7;
    const int arow_l  = (lane & 7) + (((lane >> 3) & 1) << 3);
    const int a_ga    = lane >> 4;                // A order: (r,g)(r8,g)(r,g1)(r8,g1)
    const int tau     = lane >> 3;
    const int kb_radd = ((tau >> 1) << 3) + (lane & 7);  // K: (r,g)(r,g1)(r8,g)(r8,g1)
    const int kb_ga   = tau & 1;
    const int vb_radd = ((tau & 1) << 3) + (lane & 7);   // V: (k,g)(k8,g)(k,g1)(k8,g1)
    const int vb_ga   = tau >> 1;

    // ---- S = Q K^T : 2 row-tiles x 8 n-frags, 2-pass (Qh*Kh + Qh*Kl) ----
    float accS[2][8][4];
    #pragma unroll
    for (int t = 0; t < 2; t++)
        #pragma unroll
        for (int n = 0; n < 8; n++)
            #pragma unroll
            for (int i = 0; i < 4; i++) accS[t][n][i] = 0.0f;

    #pragma unroll
    for (int kc = 0; kc < 4; kc++) {
        int ag = (kc << 1) + a_ga;
        u32 qh[2][4];
        #pragma unroll
        for (int t = 0; t < 2; t++) {
            int arow = (ww << 5) + (t << 4) + arow_l;     // arow&7 == sw
            ldsm4(qh[t], sbase + R_QH + (u32)(arow << 7) + (u32)((ag ^ sw) << 4));
        }
        int kg_ = (kc << 1) + kb_ga;
        u32 kh[16], kl[16];
        #pragma unroll
        for (int np = 0; np < 4; np++) {
            u32 roff = (u32)(((np << 4) + kb_radd) << 7) + (u32)((kg_ ^ sw) << 4);
            ldsm4(&kh[np << 2], sbase + R_KH + roff);
            ldsm4(&kl[np << 2], sbase + R_KL + roff);
        }
        #pragma unroll
        for (int t = 0; t < 2; t++)
            #pragma unroll
            for (int n = 0; n < 8; n++) {
                mma16816(accS[t][n], qh[t], &kh[n << 1]);
                mma16816(accS[t][n], qh[t], &kl[n << 1]);
            }
    }

    // ---- Softmax per row-tile in registers; pack P hi/lo A-frags (fp16) ----
    const int cb = (lane & 3) << 1;
    u32 ph[2][4][4], pl[2][4][4];
    #pragma unroll
    for (int t = 0; t < 2; t++) {
        const int r0 = (ww << 5) + (t << 4) + (lane >> 2);
        const int r1 = r0 + 8;
        int2 m0[8], m1[8];
        #pragma unroll
        for (int n = 0; n < 8; n++) {
            m0[n] = *reinterpret_cast<const int2*>(mg + (r0 << 6) + (n << 3) + cb);
            m1[n] = *reinterpret_cast<const int2*>(mg + (r1 << 6) + (n << 3) + cb);
        }
        float p0[16], p1[16];
        #pragma unroll
        for (int n = 0; n < 8; n++) {
            p0[2*n]   = (m0[n].x == 0) ? -32768.0f : accS[t][n][0] * 0.125f;
            p0[2*n+1] = (m0[n].y == 0) ? -32768.0f : accS[t][n][1] * 0.125f;
            p1[2*n]   = (m1[n].x == 0) ? -32768.0f : accS[t][n][2] * 0.125f;
            p1[2*n+1] = (m1[n].y == 0) ? -32768.0f : accS[t][n][3] * 0.125f;
        }
        float mx0 = p0[0], mx1 = p1[0];
        #pragma unroll
        for (int j = 1; j < 16; j++) { mx0 = fmaxf(mx0, p0[j]); mx1 = fmaxf(mx1, p1[j]); }
        mx0 = fmaxf(mx0, __shfl_xor_sync(0xffffffffu, mx0, 1));
        mx0 = fmaxf(mx0, __shfl_xor_sync(0xffffffffu, mx0, 2));
        mx1 = fmaxf(mx1, __shfl_xor_sync(0xffffffffu, mx1, 1));
        mx1 = fmaxf(mx1, __shfl_xor_sync(0xffffffffu, mx1, 2));
        float s0 = 0.0f, s1 = 0.0f;
        #pragma unroll
        for (int j = 0; j < 16; j++) {
            p0[j] = __expf(p0[j] - mx0); s0 += p0[j];
            p1[j] = __expf(p1[j] - mx1); s1 += p1[j];
        }
        s0 += __shfl_xor_sync(0xffffffffu, s0, 1);
        s0 += __shfl_xor_sync(0xffffffffu, s0, 2);
        s1 += __shfl_xor_sync(0xffffffffu, s1, 1);
        s1 += __shfl_xor_sync(0xffffffffu, s1, 2);
        const float i0 = 1.0f / s0, i1 = 1.0f / s1;
        #pragma unroll
        for (int j = 0; j < 16; j++) { p0[j] *= i0; p1[j] *= i1; }
        #pragma unroll
        for (int kc = 0; kc < 4; kc++) {
            ph[t][kc][0] = packh(p0[4*kc],   p0[4*kc+1]);
            ph[t][kc][1] = packh(p1[4*kc],   p1[4*kc+1]);
            ph[t][kc][2] = packh(p0[4*kc+2], p0[4*kc+3]);
            ph[t][kc][3] = packh(p1[4*kc+2], p1[4*kc+3]);
            pl[t][kc][0] = packl(ph[t][kc][0], p0[4*kc],   p0[4*kc+1]);
            pl[t][kc][1] = packl(ph[t][kc][1], p1[4*kc],   p1[4*kc+1]);
            pl[t][kc][2] = packl(ph[t][kc][2], p0[4*kc+2], p0[4*kc+3]);
            pl[t][kc][3] = packl(ph[t][kc][3], p1[4*kc+2], p1[4*kc+3]);
        }
    }

    // ---- O = P V : 3-pass (Ph*Vh + Ph*Vl + Pl*Vh); V frags shared by tiles ----
    float oacc[2][8][4];
    #pragma unroll
    for (int t = 0; t < 2; t++)
        #pragma unroll
        for (int n = 0; n < 8; n++)
            #pragma unroll
            for (int i = 0; i < 4; i++) oacc[t][n][i] = 0.0f;

    #pragma unroll
    for (int kc = 0; kc < 4; kc++) {
        u32 vh[16], vl[16];
        #pragma unroll
        for (int np = 0; np < 4; np++) {
            int vgr = (np << 1) + vb_ga;
            u32 roff = (u32)(((kc << 4) + vb_radd) << 7) + (u32)((vgr ^ sw) << 4);
            ldsm4t(&vh[np << 2], sbase + R_VH + roff);
            ldsm4t(&vl[np << 2], sbase + R_VL + roff);
        }
        #pragma unroll
        for (int t = 0; t < 2; t++)
            #pragma unroll
            for (int n = 0; n < 8; n++) {
                mma16816(oacc[t][n], ph[t][kc], &vh[n << 1]);
                mma16816(oacc[t][n], ph[t][kc], &vl[n << 1]);
                mma16816(oacc[t][n], pl[t][kc], &vh[n << 1]);
            }
    }

    // ---- Barrier, then stage O (f32, stride 68) over dead Q/K region ----
    __syncthreads();
    float* stag = reinterpret_cast<float*>(smem);
    #pragma unroll
    for (int t = 0; t < 2; t++) {
        const int r0 = (ww << 5) + (t << 4) + (lane >> 2);
        const int r1 = r0 + 8;
        #pragma unroll
        for (int n = 0; n < 8; n++) {
            *reinterpret_cast<float2*>(stag + r0 * 68 + (n << 3) + cb) =
                make_float2(oacc[t][n][0], oacc[t][n][1]);
            *reinterpret_cast<float2*>(stag + r1 * 68 + (n << 3) + cb) =
                make_float2(oacc[t][n][2], oacc[t][n][3]);
        }
    }
    __syncthreads();
    #pragma unroll
    for (int it = 0; it < 16; it++) {
        int e = (tid + (it << 6)) << 2;           // 0..4092
        int r = e >> 6, c = e & 63;
        *reinterpret_cast<float4*>(og + e) =
            *reinterpret_cast<const float4*>(stag + r * 68 + c);
    }
}

extern "C" void kernel_launch(void* const* d_in, const int* in_sizes, int n_in,
                              void* d_out, int out_size) {
    const float* q    = (const float*)d_in[0];
    const float* k    = (const float*)d_in[1];
    const float* v    = (const float*)d_in[2];
    const int*   mask = (const int*)  d_in[3];
    float*       out  = (float*)d_out;

    cudaFuncSetAttribute(attn64_f16x2p,
                         cudaFuncAttributeMaxDynamicSharedMemorySize, SMEM_BYTES);
    attn64_f16x2p<<<8192, 64, SMEM_BYTES>>>(q, k, v, mask, out);
}

// round 13
// speedup vs baseline: 1.1854x; 1.1854x over previous
#include <cuda_runtime.h>
#include <cuda_fp16.h>
#include <cstdint>

typedef uint32_t u32;

// smem regions (bytes): fp16 [64x64] tiles, rows 128B, XOR-swizzled 16B granules.
// QH only (Q residual dropped -> 2-pass QK). 40KB -> 4 CTAs/SM (reg-bound), 16 warps.
#define R_QH 0
#define R_KH 8192
#define R_KL 16384
#define R_VH 24576
#define R_VL 32768
#define SMEM_BYTES 40960
// O staging (f32, stride 68 floats, 17408B) overlays QH/KH/KL-head after the post-PV barrier.

__device__ __forceinline__ u32 smem_u32(const void* p) {
    u32 a;
    asm("{ .reg .u64 t; cvta.to.shared.u64 t, %1; cvt.u32.u64 %0, t; }" : "=r"(a) : "l"(p));
    return a;
}
__device__ __forceinline__ u32 packh(float f0, float f1) {    // lo half=f0, hi half=f1
    u32 r;
    asm("cvt.rn.f16x2.f32 %0, %1, %2;" : "=r"(r) : "f"(f1), "f"(f0));
    return r;
}
__device__ __forceinline__ u32 packl(u32 h, float f0, float f1) {
    __half2 hh = *reinterpret_cast<__half2*>(&h);
    float2 hf = __half22float2(hh);               // .x = low, .y = high
    return packh(f0 - hf.x, f1 - hf.y);
}
__device__ __forceinline__ void ldsm4(u32* r, u32 addr) {
    asm volatile("ldmatrix.sync.aligned.m8n8.x4.shared.b16 {%0,%1,%2,%3}, [%4];"
        : "=r"(r[0]), "=r"(r[1]), "=r"(r[2]), "=r"(r[3]) : "r"(addr));
}
__device__ __forceinline__ void ldsm4t(u32* r, u32 addr) {
    asm volatile("ldmatrix.sync.aligned.m8n8.x4.trans.shared.b16 {%0,%1,%2,%3}, [%4];"
        : "=r"(r[0]), "=r"(r[1]), "=r"(r[2]), "=r"(r[3]) : "r"(addr));
}
__device__ __forceinline__ void mma16816(float* c, const u32* a, const u32* b) {
    asm volatile(
        "mma.sync.aligned.m16n8k16.row.col.f32.f16.f16.f32 "
        "{%0,%1,%2,%3}, {%4,%5,%6,%7}, {%8,%9}, {%0,%1,%2,%3};"
        : "+f"(c[0]), "+f"(c[1]), "+f"(c[2]), "+f"(c[3])
        : "r"(a[0]), "r"(a[1]), "r"(a[2]), "r"(a[3]), "r"(b[0]), "r"(b[1]));
}

__global__ void __launch_bounds__(128, 4)
attn64_r13(const float* __restrict__ qg_, const float* __restrict__ kg_,
           const float* __restrict__ vg_, const int* __restrict__ mg_,
           float* __restrict__ og_)
{
    extern __shared__ char smem[];
    const u32 sbase = smem_u32(smem);
    const int tid  = threadIdx.x;
    const int lane = tid & 31;
    const int w    = tid >> 5;                    // warp -> S rows 16w..16w+15

    const int pg = blockIdx.x;                    // one 64x64x64 problem per CTA
    const float* qg = qg_ + (size_t)pg * 4096;
    const float* kg = kg_ + (size_t)pg * 4096;
    const float* vg = vg_ + (size_t)pg * 4096;
    const int*   mg = mg_ + (size_t)(pg >> 9) * 4096;
    float*       og = og_ + (size_t)pg * 4096;

    // ---- Stage: fp32 -> fp16 (Q hi only; K,V hi+lo), swizzled granule^(row&7) ----
    // 512 granule-pairs per tensor, 128 threads -> 4 iterations.
    #pragma unroll
    for (int it = 0; it < 4; it++) {
        int idx = tid + (it << 7);                // 0..511
        int e = idx << 3;                         // 8 source floats
        int r = idx >> 3;                         // row 0..63
        int h = idx & 7;                          // granule 0..7
        int off = (r << 7) + ((h ^ (r & 7)) << 4);
        float4 f0, f1;
        uint4 hq, lq;

        f0 = *reinterpret_cast<const float4*>(qg + e);
        f1 = *reinterpret_cast<const float4*>(qg + e + 4);
        hq.x = packh(f0.x, f0.y); hq.y = packh(f0.z, f0.w);
        hq.z = packh(f1.x, f1.y); hq.w = packh(f1.z, f1.w);
        *reinterpret_cast<uint4*>(smem + R_QH + off) = hq;   // no Q residual

        f0 = *reinterpret_cast<const float4*>(kg + e);
        f1 = *reinterpret_cast<const float4*>(kg + e + 4);
        hq.x = packh(f0.x, f0.y); hq.y = packh(f0.z, f0.w);
        hq.z = packh(f1.x, f1.y); hq.w = packh(f1.z, f1.w);
        lq.x = packl(hq.x, f0.x, f0.y); lq.y = packl(hq.y, f0.z, f0.w);
        lq.z = packl(hq.z, f1.x, f1.y); lq.w = packl(hq.w, f1.z, f1.w);
        *reinterpret_cast<uint4*>(smem + R_KH + off) = hq;
        *reinterpret_cast<uint4*>(smem + R_KL + off) = lq;

        f0 = *reinterpret_cast<const float4*>(vg + e);
        f1 = *reinterpret_cast<const float4*>(vg + e + 4);
        hq.x = packh(f0.x, f0.y); hq.y = packh(f0.z, f0.w);
        hq.z = packh(f1.x, f1.y); hq.w = packh(f1.z, f1.w);
        lq.x = packl(hq.x, f0.x, f0.y); lq.y = packl(hq.y, f0.z, f0.w);
        lq.z = packl(hq.z, f1.x, f1.y); lq.w = packl(hq.w, f1.z, f1.w);
        *reinterpret_cast<uint4*>(smem + R_VH + off) = hq;
        *reinterpret_cast<uint4*>(smem + R_VL + off) = lq;
    }
    __syncthreads();

    // ---- ldmatrix address templates (validated rounds 9/10/12) ----
    const int sw      = lane & 7;
    const int a_row   = (w << 4) + (lane & 7) + (((lane >> 3) & 1) << 3);
    const int a_ga    = lane >> 4;                // A order: (r,g)(r8,g)(r,g1)(r8,g1)
    const u32 a_base  = sbase + (u32)(a_row << 7);
    const int tau     = lane >> 3;
    const int kb_radd = ((tau >> 1) << 3) + (lane & 7);  // K: (r,g)(r,g1)(r8,g)(r8,g1)
    const int kb_ga   = tau & 1;
    const int vb_radd = ((tau & 1) << 3) + (lane & 7);   // V: (k,g)(k8,g)(k,g1)(k8,g1)
    const int vb_ga   = tau >> 1;

    // ---- S = Q K^T : 2-pass (Qh*Kh + Qh*Kl), 8 n-frags, fp32 accum ----
    float accS[8][4];
    #pragma unroll
    for (int n = 0; n < 8; n++)
        #pragma unroll
        for (int i = 0; i < 4; i++) accS[n][i] = 0.0f;

    #pragma unroll
    for (int kc = 0; kc < 4; kc++) {
        int ag = (kc << 1) + a_ga;
        u32 qh[4];
        ldsm4(qh, a_base + R_QH + ((ag ^ sw) << 4));
        int kg_ = (kc << 1) + kb_ga;
        u32 kh[16], kl[16];
        #pragma unroll
        for (int np = 0; np < 4; np++) {
            u32 roff = (u32)(((np << 4) + kb_radd) << 7) + (u32)((kg_ ^ sw) << 4);
            ldsm4(&kh[np << 2], sbase + R_KH + roff);
            ldsm4(&kl[np << 2], sbase + R_KL + roff);
        }
        #pragma unroll
        for (int n = 0; n < 8; n++) {
            mma16816(accS[n], qh, &kh[n << 1]);
            mma16816(accS[n], qh, &kl[n << 1]);
        }
    }

    // ---- Mask fetch (L2-resident) ----
    const int r0 = (w << 4) + (lane >> 2);
    const int r1 = r0 + 8;
    const int cb = (lane & 3) << 1;
    int2 m0[8], m1[8];
    #pragma unroll
    for (int n = 0; n < 8; n++) {
        m0[n] = *reinterpret_cast<const int2*>(mg + (r0 << 6) + (n << 3) + cb);
        m1[n] = *reinterpret_cast<const int2*>(mg + (r1 << 6) + (n << 3) + cb);
    }

    // ---- Softmax fully in registers (quad shuffles over the 4 col-lanes) ----
    float p0[16], p1[16];
    #pragma unroll
    for (int n = 0; n < 8; n++) {
        p0[2*n]   = (m0[n].x == 0) ? -32768.0f : accS[n][0] * 0.125f;
        p0[2*n+1] = (m0[n].y == 0) ? -32768.0f : accS[n][1] * 0.125f;
        p1[2*n]   = (m1[n].x == 0) ? -32768.0f : accS[n][2] * 0.125f;
        p1[2*n+1] = (m1[n].y == 0) ? -32768.0f : accS[n][3] * 0.125f;
    }
    float mx0 = p0[0], mx1 = p1[0];
    #pragma unroll
    for (int j = 1; j < 16; j++) { mx0 = fmaxf(mx0, p0[j]); mx1 = fmaxf(mx1, p1[j]); }
    mx0 = fmaxf(mx0, __shfl_xor_sync(0xffffffffu, mx0, 1));
    mx0 = fmaxf(mx0, __shfl_xor_sync(0xffffffffu, mx0, 2));
    mx1 = fmaxf(mx1, __shfl_xor_sync(0xffffffffu, mx1, 1));
    mx1 = fmaxf(mx1, __shfl_xor_sync(0xffffffffu, mx1, 2));
    float s0 = 0.0f, s1 = 0.0f;
    #pragma unroll
    for (int j = 0; j < 16; j++) {
        p0[j] = __expf(p0[j] - mx0); s0 += p0[j];
        p1[j] = __expf(p1[j] - mx1); s1 += p1[j];
    }
    s0 += __shfl_xor_sync(0xffffffffu, s0, 1);
    s0 += __shfl_xor_sync(0xffffffffu, s0, 2);
    s1 += __shfl_xor_sync(0xffffffffu, s1, 1);
    s1 += __shfl_xor_sync(0xffffffffu, s1, 2);
    const float i0 = 1.0f / s0, i1 = 1.0f / s1;
    #pragma unroll
    for (int j = 0; j < 16; j++) { p0[j] *= i0; p1[j] *= i1; }

    // ---- Pack P into A-fragments (hi,lo fp16) in registers ----
    u32 ph[4][4], pl[4][4];
    #pragma unroll
    for (int kc = 0; kc < 4; kc++) {
        ph[kc][0] = packh(p0[4*kc],   p0[4*kc+1]);
        ph[kc][1] = packh(p1[4*kc],   p1[4*kc+1]);
        ph[kc][2] = packh(p0[4*kc+2], p0[4*kc+3]);
        ph[kc][3] = packh(p1[4*kc+2], p1[4*kc+3]);
        pl[kc][0] = packl(ph[kc][0], p0[4*kc],   p0[4*kc+1]);
        pl[kc][1] = packl(ph[kc][1], p1[4*kc],   p1[4*kc+1]);
        pl[kc][2] = packl(ph[kc][2], p0[4*kc+2], p0[4*kc+3]);
        pl[kc][3] = packl(ph[kc][3], p1[4*kc+2], p1[4*kc+3]);
    }

    // ---- O = P V : 3-pass (Ph*Vh + Ph*Vl + Pl*Vh), V frags via ldsm.trans ----
    float oacc[8][4];
    #pragma unroll
    for (int n = 0; n < 8; n++)
        #pragma unroll
        for (int i = 0; i < 4; i++) oacc[n][i] = 0.0f;

    #pragma unroll
    for (int kc = 0; kc < 4; kc++) {
        u32 vh[16], vl[16];
        #pragma unroll
        for (int np = 0; np < 4; np++) {
            int vgr = (np << 1) + vb_ga;
            u32 roff = (u32)(((kc << 4) + vb_radd) << 7) + (u32)((vgr ^ sw) << 4);
            ldsm4t(&vh[np << 2], sbase + R_VH + roff);
            ldsm4t(&vl[np << 2], sbase + R_VL + roff);
        }
        #pragma unroll
        for (int n = 0; n < 8; n++) {
            mma16816(oacc[n], ph[kc], &vh[n << 1]);
            mma16816(oacc[n], ph[kc], &vl[n << 1]);
            mma16816(oacc[n], pl[kc], &vh[n << 1]);
        }
    }

    // ---- Barrier (all smem tiles dead), stage O f32 stride-68, coalesced out ----
    __syncthreads();
    float* stag = reinterpret_cast<float*>(smem);
    #pragma unroll
    for (int n = 0; n < 8; n++) {
        *reinterpret_cast<float2*>(stag + r0 * 68 + (n << 3) + cb) =
            make_float2(oacc[n][0], oacc[n][1]);
        *reinterpret_cast<float2*>(stag + r1 * 68 + (n << 3) + cb) =
            make_float2(oacc[n][2], oacc[n][3]);
    }
    __syncthreads();
    #pragma unroll
    for (int it = 0; it < 8; it++) {
        int e = (tid + (it << 7)) << 2;
        int r = e >> 6, c = e & 63;
        *reinterpret_cast<float4*>(og + e) =
            *reinterpret_cast<const float4*>(stag + r * 68 + c);
    }
}

extern "C" void kernel_launch(void* const* d_in, const int* in_sizes, int n_in,
                              void* d_out, int out_size) {
    const float* q    = (const float*)d_in[0];
    const float* k    = (const float*)d_in[1];
    const float* v    = (const float*)d_in[2];
    const int*   mask = (const int*)  d_in[3];
    float*       out  = (float*)d_out;

    cudaFuncSetAttribute(attn64_r13,
                         cudaFuncAttributeMaxDynamicSharedMemorySize, SMEM_BYTES);
    attn64_r13<<<8192, 128, SMEM_BYTES>>>(q, k, v, mask, out);
}

// round 14
// speedup vs baseline: 1.2563x; 1.0598x over previous
#include <cuda_runtime.h>
#include <cuda_fp16.h>
#include <cstdint>

typedef uint32_t u32;

// smem regions (bytes): fp16 [64x64] tiles, rows 128B, XOR-swizzled 16B granules.
// QH only (2-pass QK), VH only (V residual dropped; PV = (Ph+Pl)*Vh). 32KB.
#define R_QH 0
#define R_KH 8192
#define R_KL 16384
#define R_VH 24576
#define SMEM_BYTES 32768

__device__ __forceinline__ u32 smem_u32(const void* p) {
    u32 a;
    asm("{ .reg .u64 t; cvta.to.shared.u64 t, %1; cvt.u32.u64 %0, t; }" : "=r"(a) : "l"(p));
    return a;
}
__device__ __forceinline__ u32 packh(float f0, float f1) {    // lo half=f0, hi half=f1
    u32 r;
    asm("cvt.rn.f16x2.f32 %0, %1, %2;" : "=r"(r) : "f"(f1), "f"(f0));
    return r;
}
__device__ __forceinline__ u32 packl(u32 h, float f0, float f1) {
    __half2 hh = *reinterpret_cast<__half2*>(&h);
    float2 hf = __half22float2(hh);               // .x = low, .y = high
    return packh(f0 - hf.x, f1 - hf.y);
}
__device__ __forceinline__ void ldsm4(u32* r, u32 addr) {
    asm volatile("ldmatrix.sync.aligned.m8n8.x4.shared.b16 {%0,%1,%2,%3}, [%4];"
        : "=r"(r[0]), "=r"(r[1]), "=r"(r[2]), "=r"(r[3]) : "r"(addr));
}
__device__ __forceinline__ void ldsm4t(u32* r, u32 addr) {
    asm volatile("ldmatrix.sync.aligned.m8n8.x4.trans.shared.b16 {%0,%1,%2,%3}, [%4];"
        : "=r"(r[0]), "=r"(r[1]), "=r"(r[2]), "=r"(r[3]) : "r"(addr));
}
__device__ __forceinline__ void mma16816(float* c, const u32* a, const u32* b) {
    asm volatile(
        "mma.sync.aligned.m16n8k16.row.col.f32.f16.f16.f32 "
        "{%0,%1,%2,%3}, {%4,%5,%6,%7}, {%8,%9}, {%0,%1,%2,%3};"
        : "+f"(c[0]), "+f"(c[1]), "+f"(c[2]), "+f"(c[3])
        : "r"(a[0]), "r"(a[1]), "r"(a[2]), "r"(a[3]), "r"(b[0]), "r"(b[1]));
}

__global__ void __launch_bounds__(128, 4)
attn64_r14(const float* __restrict__ qg_, const float* __restrict__ kg_,
           const float* __restrict__ vg_, const int* __restrict__ mg_,
           float* __restrict__ og_)
{
    extern __shared__ char smem[];
    const u32 sbase = smem_u32(smem);
    const int tid  = threadIdx.x;
    const int lane = tid & 31;
    const int w    = tid >> 5;                    // warp -> S rows 16w..16w+15

    const int pg = blockIdx.x;                    // one 64x64x64 problem per CTA
    const float* qg = qg_ + (size_t)pg * 4096;
    const float* kg = kg_ + (size_t)pg * 4096;
    const float* vg = vg_ + (size_t)pg * 4096;
    const int*   mg = mg_ + (size_t)(pg >> 9) * 4096;
    float*       og = og_ + (size_t)pg * 4096;

    // ---- Stage: fp32 -> fp16 (Q hi; K hi+lo; V hi), swizzled granule^(row&7) ----
    #pragma unroll
    for (int it = 0; it < 4; it++) {
        int idx = tid + (it << 7);                // 0..511
        int e = idx << 3;                         // 8 source floats
        int r = idx >> 3;                         // row 0..63
        int h = idx & 7;                          // granule 0..7
        int off = (r << 7) + ((h ^ (r & 7)) << 4);
        float4 f0, f1;
        uint4 hq, lq;

        f0 = *reinterpret_cast<const float4*>(qg + e);
        f1 = *reinterpret_cast<const float4*>(qg + e + 4);
        hq.x = packh(f0.x, f0.y); hq.y = packh(f0.z, f0.w);
        hq.z = packh(f1.x, f1.y); hq.w = packh(f1.z, f1.w);
        *reinterpret_cast<uint4*>(smem + R_QH + off) = hq;

        f0 = *reinterpret_cast<const float4*>(kg + e);
        f1 = *reinterpret_cast<const float4*>(kg + e + 4);
        hq.x = packh(f0.x, f0.y); hq.y = packh(f0.z, f0.w);
        hq.z = packh(f1.x, f1.y); hq.w = packh(f1.z, f1.w);
        lq.x = packl(hq.x, f0.x, f0.y); lq.y = packl(hq.y, f0.z, f0.w);
        lq.z = packl(hq.z, f1.x, f1.y); lq.w = packl(hq.w, f1.z, f1.w);
        *reinterpret_cast<uint4*>(smem + R_KH + off) = hq;
        *reinterpret_cast<uint4*>(smem + R_KL + off) = lq;

        f0 = *reinterpret_cast<const float4*>(vg + e);
        f1 = *reinterpret_cast<const float4*>(vg + e + 4);
        hq.x = packh(f0.x, f0.y); hq.y = packh(f0.z, f0.w);
        hq.z = packh(f1.x, f1.y); hq.w = packh(f1.z, f1.w);
        *reinterpret_cast<uint4*>(smem + R_VH + off) = hq;   // no V residual
    }
    __syncthreads();

    // ---- ldmatrix address templates (validated rounds 9/10/12/13) ----
    const int sw      = lane & 7;
    const int a_row   = (w << 4) + (lane & 7) + (((lane >> 3) & 1) << 3);
    const int a_ga    = lane >> 4;                // A order: (r,g)(r8,g)(r,g1)(r8,g1)
    const u32 a_base  = sbase + (u32)(a_row << 7);
    const int tau     = lane >> 3;
    const int kb_radd = ((tau >> 1) << 3) + (lane & 7);  // K: (r,g)(r,g1)(r8,g)(r8,g1)
    const int kb_ga   = tau & 1;
    const int vb_radd = ((tau & 1) << 3) + (lane & 7);   // V: (k,g)(k8,g)(k,g1)(k8,g1)
    const int vb_ga   = tau >> 1;

    // ---- S = Q K^T : 2-pass (Qh*Kh + Qh*Kl), 8 n-frags, fp32 accum ----
    float accS[8][4];
    #pragma unroll
    for (int n = 0; n < 8; n++)
        #pragma unroll
        for (int i = 0; i < 4; i++) accS[n][i] = 0.0f;

    #pragma unroll
    for (int kc = 0; kc < 4; kc++) {
        int ag = (kc << 1) + a_ga;
        u32 qh[4];
        ldsm4(qh, a_base + R_QH + ((ag ^ sw) << 4));
        int kg_ = (kc << 1) + kb_ga;
        u32 kh[16], kl[16];
        #pragma unroll
        for (int np = 0; np < 4; np++) {
            u32 roff = (u32)(((np << 4) + kb_radd) << 7) + (u32)((kg_ ^ sw) << 4);
            ldsm4(&kh[np << 2], sbase + R_KH + roff);
            ldsm4(&kl[np << 2], sbase + R_KL + roff);
        }
        #pragma unroll
        for (int n = 0; n < 8; n++) {
            mma16816(accS[n], qh, &kh[n << 1]);
            mma16816(accS[n], qh, &kl[n << 1]);
        }
    }

    // ---- Mask fetch (L2-resident) ----
    const int r0 = (w << 4) + (lane >> 2);
    const int r1 = r0 + 8;
    const int cb = (lane & 3) << 1;
    int2 m0[8], m1[8];
    #pragma unroll
    for (int n = 0; n < 8; n++) {
        m0[n] = *reinterpret_cast<const int2*>(mg + (r0 << 6) + (n << 3) + cb);
        m1[n] = *reinterpret_cast<const int2*>(mg + (r1 << 6) + (n << 3) + cb);
    }

    // ---- Softmax fully in registers (quad shuffles over the 4 col-lanes) ----
    float p0[16], p1[16];
    #pragma unroll
    for (int n = 0; n < 8; n++) {
        p0[2*n]   = (m0[n].x == 0) ? -32768.0f : accS[n][0] * 0.125f;
        p0[2*n+1] = (m0[n].y == 0) ? -32768.0f : accS[n][1] * 0.125f;
        p1[2*n]   = (m1[n].x == 0) ? -32768.0f : accS[n][2] * 0.125f;
        p1[2*n+1] = (m1[n].y == 0) ? -32768.0f : accS[n][3] * 0.125f;
    }
    float mx0 = p0[0], mx1 = p1[0];
    #pragma unroll
    for (int j = 1; j < 16; j++) { mx0 = fmaxf(mx0, p0[j]); mx1 = fmaxf(mx1, p1[j]); }
    mx0 = fmaxf(mx0, __shfl_xor_sync(0xffffffffu, mx0, 1));
    mx0 = fmaxf(mx0, __shfl_xor_sync(0xffffffffu, mx0, 2));
    mx1 = fmaxf(mx1, __shfl_xor_sync(0xffffffffu, mx1, 1));
    mx1 = fmaxf(mx1, __shfl_xor_sync(0xffffffffu, mx1, 2));
    float s0 = 0.0f, s1 = 0.0f;
    #pragma unroll
    for (int j = 0; j < 16; j++) {
        p0[j] = __expf(p0[j] - mx0); s0 += p0[j];
        p1[j] = __expf(p1[j] - mx1); s1 += p1[j];
    }
    s0 += __shfl_xor_sync(0xffffffffu, s0, 1);
    s0 += __shfl_xor_sync(0xffffffffu, s0, 2);
    s1 += __shfl_xor_sync(0xffffffffu, s1, 1);
    s1 += __shfl_xor_sync(0xffffffffu, s1, 2);
    const float i0 = 1.0f / s0, i1 = 1.0f / s1;
    #pragma unroll
    for (int j = 0; j < 16; j++) { p0[j] *= i0; p1[j] *= i1; }

    // ---- Pack P into A-fragments (hi,lo fp16) in registers ----
    u32 ph[4][4], pl[4][4];
    #pragma unroll
    for (int kc = 0; kc < 4; kc++) {
        ph[kc][0] = packh(p0[4*kc],   p0[4*kc+1]);
        ph[kc][1] = packh(p1[4*kc],   p1[4*kc+1]);
        ph[kc][2] = packh(p0[4*kc+2], p0[4*kc+3]);
        ph[kc][3] = packh(p1[4*kc+2], p1[4*kc+3]);
        pl[kc][0] = packl(ph[kc][0], p0[4*kc],   p0[4*kc+1]);
        pl[kc][1] = packl(ph[kc][1], p1[4*kc],   p1[4*kc+1]);
        pl[kc][2] = packl(ph[kc][2], p0[4*kc+2], p0[4*kc+3]);
        pl[kc][3] = packl(ph[kc][3], p1[4*kc+2], p1[4*kc+3]);
    }

    // ---- O = P V : 2-pass ((Ph + Pl) * Vh), V frags via ldsm.trans ----
    float oacc[8][4];
    #pragma unroll
    for (int n = 0; n < 8; n++)
        #pragma unroll
        for (int i = 0; i < 4; i++) oacc[n][i] = 0.0f;

    #pragma unroll
    for (int kc = 0; kc < 4; kc++) {
        u32 vh[16];
        #pragma unroll
        for (int np = 0; np < 4; np++) {
            int vgr = (np << 1) + vb_ga;
            u32 roff = (u32)(((kc << 4) + vb_radd) << 7) + (u32)((vgr ^ sw) << 4);
            ldsm4t(&vh[np << 2], sbase + R_VH + roff);
        }
        #pragma unroll
        for (int n = 0; n < 8; n++) {
            mma16816(oacc[n], ph[kc], &vh[n << 1]);
            mma16816(oacc[n], pl[kc], &vh[n << 1]);
        }
    }

    // ---- Direct coalesced-sector stores (32B row segments per lane quartet) ----
    #pragma unroll
    for (int n = 0; n < 8; n++) {
        *reinterpret_cast<float2*>(og + (r0 << 6) + (n << 3) + cb) =
            make_float2(oacc[n][0], oacc[n][1]);
        *reinterpret_cast<float2*>(og + (r1 << 6) + (n << 3) + cb) =
            make_float2(oacc[n][2], oacc[n][3]);
    }
}

extern "C" void kernel_launch(void* const* d_in, const int* in_sizes, int n_in,
                              void* d_out, int out_size) {
    const float* q    = (const float*)d_in[0];
    const float* k    = (const float*)d_in[1];
    const float* v    = (const float*)d_in[2];
    const int*   mask = (const int*)  d_in[3];
    float*       out  = (float*)d_out;

    cudaFuncSetAttribute(attn64_r14,
                         cudaFuncAttributeMaxDynamicSharedMemorySize, SMEM_BYTES);
    attn64_r14<<<8192, 128, SMEM_BYTES>>>(q, k, v, mask, out);
}

// round 15
// speedup vs baseline: 1.5473x; 1.2317x over previous
#include <cuda_runtime.h>
#include <cuda_fp16.h>
#include <cstdint>

typedef uint32_t u32;
typedef unsigned long long u64;

// smem regions (bytes): fp16 [64x64] tiles, rows 128B, XOR-swizzled 16B granules.
// Pure-fp16 QK (no K residual); PV = (Ph+Pl)*Vh. 24KB -> 5 CTAs/SM target.
#define R_QH 0
#define R_KH 8192
#define R_VH 16384
#define SMEM_BYTES 24576

// Packed mask bits: 16 batches x 64 rows, bit c = mask[b][r][c].
__device__ u64 g_mask_bits[16 * 64];

__device__ __forceinline__ u32 smem_u32(const void* p) {
    u32 a;
    asm("{ .reg .u64 t; cvta.to.shared.u64 t, %1; cvt.u32.u64 %0, t; }" : "=r"(a) : "l"(p));
    return a;
}
__device__ __forceinline__ u32 packh(float f0, float f1) {    // lo half=f0, hi half=f1
    u32 r;
    asm("cvt.rn.f16x2.f32 %0, %1, %2;" : "=r"(r) : "f"(f1), "f"(f0));
    return r;
}
__device__ __forceinline__ u32 packl(u32 h, float f0, float f1) {
    __half2 hh = *reinterpret_cast<__half2*>(&h);
    float2 hf = __half22float2(hh);               // .x = low, .y = high
    return packh(f0 - hf.x, f1 - hf.y);
}
__device__ __forceinline__ void ldsm4(u32* r, u32 addr) {
    asm volatile("ldmatrix.sync.aligned.m8n8.x4.shared.b16 {%0,%1,%2,%3}, [%4];"
        : "=r"(r[0]), "=r"(r[1]), "=r"(r[2]), "=r"(r[3]) : "r"(addr));
}
__device__ __forceinline__ void ldsm4t(u32* r, u32 addr) {
    asm volatile("ldmatrix.sync.aligned.m8n8.x4.trans.shared.b16 {%0,%1,%2,%3}, [%4];"
        : "=r"(r[0]), "=r"(r[1]), "=r"(r[2]), "=r"(r[3]) : "r"(addr));
}
__device__ __forceinline__ void mma16816(float* c, const u32* a, const u32* b) {
    asm volatile(
        "mma.sync.aligned.m16n8k16.row.col.f32.f16.f16.f32 "
        "{%0,%1,%2,%3}, {%4,%5,%6,%7}, {%8,%9}, {%0,%1,%2,%3};"
        : "+f"(c[0]), "+f"(c[1]), "+f"(c[2]), "+f"(c[3])
        : "r"(a[0]), "r"(a[1]), "r"(a[2]), "r"(a[3]), "r"(b[0]), "r"(b[1]));
}

// ---- Pre-kernel: pack mask ints into per-row u64 bitmasks (runs once/graph) ----
__global__ void pack_mask_kernel(const int* __restrict__ mg) {
    const int b = blockIdx.x;                     // 0..15
    const int r = threadIdx.x;                    // 0..63
    const int4* row = reinterpret_cast<const int4*>(mg + b * 4096 + r * 64);
    u64 bits = 0;
    #pragma unroll
    for (int j = 0; j < 16; j++) {
        int4 m = row[j];
        u64 b4 = (m.x != 0 ? 1ull : 0ull) | (m.y != 0 ? 2ull : 0ull)
               | (m.z != 0 ? 4ull : 0ull) | (m.w != 0 ? 8ull : 0ull);
        bits |= b4 << (j << 2);
    }
    g_mask_bits[b * 64 + r] = bits;
}

__global__ void __launch_bounds__(128, 5)
attn64_r15(const float* __restrict__ qg_, const float* __restrict__ kg_,
           const float* __restrict__ vg_, float* __restrict__ og_)
{
    extern __shared__ char smem[];
    const u32 sbase = smem_u32(smem);
    const int tid  = threadIdx.x;
    const int lane = tid & 31;
    const int w    = tid >> 5;                    // warp -> S rows 16w..16w+15

    const int pg = blockIdx.x;                    // one 64x64x64 problem per CTA
    const float* qg = qg_ + (size_t)pg * 4096;
    const float* kg = kg_ + (size_t)pg * 4096;
    const float* vg = vg_ + (size_t)pg * 4096;
    float*       og = og_ + (size_t)pg * 4096;

    // ---- Stage: fp32 -> fp16 hi (Q, K, V), swizzled granule^(row&7) ----
    #pragma unroll
    for (int it = 0; it < 4; it++) {
        int idx = tid + (it << 7);                // 0..511
        int e = idx << 3;                         // 8 source floats
        int r = idx >> 3;                         // row 0..63
        int h = idx & 7;                          // granule 0..7
        int off = (r << 7) + ((h ^ (r & 7)) << 4);
        float4 f0, f1;
        uint4 hq;

        f0 = *reinterpret_cast<const float4*>(qg + e);
        f1 = *reinterpret_cast<const float4*>(qg + e + 4);
        hq.x = packh(f0.x, f0.y); hq.y = packh(f0.z, f0.w);
        hq.z = packh(f1.x, f1.y); hq.w = packh(f1.z, f1.w);
        *reinterpret_cast<uint4*>(smem + R_QH + off) = hq;

        f0 = *reinterpret_cast<const float4*>(kg + e);
        f1 = *reinterpret_cast<const float4*>(kg + e + 4);
        hq.x = packh(f0.x, f0.y); hq.y = packh(f0.z, f0.w);
        hq.z = packh(f1.x, f1.y); hq.w = packh(f1.z, f1.w);
        *reinterpret_cast<uint4*>(smem + R_KH + off) = hq;   // no K residual

        f0 = *reinterpret_cast<const float4*>(vg + e);
        f1 = *reinterpret_cast<const float4*>(vg + e + 4);
        hq.x = packh(f0.x, f0.y); hq.y = packh(f0.z, f0.w);
        hq.z = packh(f1.x, f1.y); hq.w = packh(f1.z, f1.w);
        *reinterpret_cast<uint4*>(smem + R_VH + off) = hq;   // no V residual
    }
    __syncthreads();

    // ---- ldmatrix address templates (validated rounds 9-14) ----
    const int sw      = lane & 7;
    const int a_row   = (w << 4) + (lane & 7) + (((lane >> 3) & 1) << 3);
    const int a_ga    = lane >> 4;                // A order: (r,g)(r8,g)(r,g1)(r8,g1)
    const u32 a_base  = sbase + (u32)(a_row << 7);
    const int tau     = lane >> 3;
    const int kb_radd = ((tau >> 1) << 3) + (lane & 7);  // K: (r,g)(r,g1)(r8,g)(r8,g1)
    const int kb_ga   = tau & 1;
    const int vb_radd = ((tau & 1) << 3) + (lane & 7);   // V: (k,g)(k8,g)(k,g1)(k8,g1)
    const int vb_ga   = tau >> 1;

    // ---- S = Q K^T : pure fp16 (Qh*Kh), 8 n-frags, fp32 accum ----
    float accS[8][4];
    #pragma unroll
    for (int n = 0; n < 8; n++)
        #pragma unroll
        for (int i = 0; i < 4; i++) accS[n][i] = 0.0f;

    #pragma unroll
    for (int kc = 0; kc < 4; kc++) {
        int ag = (kc << 1) + a_ga;
        u32 qh[4];
        ldsm4(qh, a_base + R_QH + ((ag ^ sw) << 4));
        int kg_ = (kc << 1) + kb_ga;
        u32 kh[16];
        #pragma unroll
        for (int np = 0; np < 4; np++) {
            u32 roff = (u32)(((np << 4) + kb_radd) << 7) + (u32)((kg_ ^ sw) << 4);
            ldsm4(&kh[np << 2], sbase + R_KH + roff);
        }
        #pragma unroll
        for (int n = 0; n < 8; n++)
            mma16816(accS[n], qh, &kh[n << 1]);
    }

    // ---- Mask: 2 packed u64 loads (pre-packed by pack_mask_kernel) ----
    const int r0 = (w << 4) + (lane >> 2);
    const int r1 = r0 + 8;
    const int cb = (lane & 3) << 1;
    const u64* mbase = g_mask_bits + ((pg >> 9) << 6);
    const u64 mb0 = mbase[r0];
    const u64 mb1 = mbase[r1];

    // ---- Softmax fully in registers (quad shuffles over the 4 col-lanes) ----
    float p0[16], p1[16];
    #pragma unroll
    for (int n = 0; n < 8; n++) {
        int c0 = (n << 3) + cb;
        p0[2*n]   = ((mb0 >> c0) & 1ull)       ? accS[n][0] * 0.125f : -32768.0f;
        p0[2*n+1] = ((mb0 >> (c0 + 1)) & 1ull) ? accS[n][1] * 0.125f : -32768.0f;
        p1[2*n]   = ((mb1 >> c0) & 1ull)       ? accS[n][2] * 0.125f : -32768.0f;
        p1[2*n+1] = ((mb1 >> (c0 + 1)) & 1ull) ? accS[n][3] * 0.125f : -32768.0f;
    }
    float mx0 = p0[0], mx1 = p1[0];
    #pragma unroll
    for (int j = 1; j < 16; j++) { mx0 = fmaxf(mx0, p0[j]); mx1 = fmaxf(mx1, p1[j]); }
    mx0 = fmaxf(mx0, __shfl_xor_sync(0xffffffffu, mx0, 1));
    mx0 = fmaxf(mx0, __shfl_xor_sync(0xffffffffu, mx0, 2));
    mx1 = fmaxf(mx1, __shfl_xor_sync(0xffffffffu, mx1, 1));
    mx1 = fmaxf(mx1, __shfl_xor_sync(0xffffffffu, mx1, 2));
    float s0 = 0.0f, s1 = 0.0f;
    #pragma unroll
    for (int j = 0; j < 16; j++) {
        p0[j] = __expf(p0[j] - mx0); s0 += p0[j];
        p1[j] = __expf(p1[j] - mx1); s1 += p1[j];
    }
    s0 += __shfl_xor_sync(0xffffffffu, s0, 1);
    s0 += __shfl_xor_sync(0xffffffffu, s0, 2);
    s1 += __shfl_xor_sync(0xffffffffu, s1, 1);
    s1 += __shfl_xor_sync(0xffffffffu, s1, 2);
    const float i0 = 1.0f / s0, i1 = 1.0f / s1;
    #pragma unroll
    for (int j = 0; j < 16; j++) { p0[j] *= i0; p1[j] *= i1; }

    // ---- Pack P into A-fragments (hi,lo fp16) in registers ----
    u32 ph[4][4], pl[4][4];
    #pragma unroll
    for (int kc = 0; kc < 4; kc++) {
        ph[kc][0] = packh(p0[4*kc],   p0[4*kc+1]);
        ph[kc][1] = packh(p1[4*kc],   p1[4*kc+1]);
        ph[kc][2] = packh(p0[4*kc+2], p0[4*kc+3]);
        ph[kc][3] = packh(p1[4*kc+2], p1[4*kc+3]);
        pl[kc][0] = packl(ph[kc][0], p0[4*kc],   p0[4*kc+1]);
        pl[kc][1] = packl(ph[kc][1], p1[4*kc],   p1[4*kc+1]);
        pl[kc][2] = packl(ph[kc][2], p0[4*kc+2], p0[4*kc+3]);
        pl[kc][3] = packl(ph[kc][3], p1[4*kc+2], p1[4*kc+3]);
    }

    // ---- O = P V : 2-pass ((Ph + Pl) * Vh), V frags via ldsm.trans ----
    float oacc[8][4];
    #pragma unroll
    for (int n = 0; n < 8; n++)
        #pragma unroll
        for (int i = 0; i < 4; i++) oacc[n][i] = 0.0f;

    #pragma unroll
    for (int kc = 0; kc < 4; kc++) {
        u32 vh[16];
        #pragma unroll
        for (int np = 0; np < 4; np++) {
            int vgr = (np << 1) + vb_ga;
            u32 roff = (u32)(((kc << 4) + vb_radd) << 7) + (u32)((vgr ^ sw) << 4);
            ldsm4t(&vh[np << 2], sbase + R_VH + roff);
        }
        #pragma unroll
        for (int n = 0; n < 8; n++) {
            mma16816(oacc[n], ph[kc], &vh[n << 1]);
            mma16816(oacc[n], pl[kc], &vh[n << 1]);
        }
    }

    // ---- Direct coalesced-sector stores (32B row segments per lane quartet) ----
    #pragma unroll
    for (int n = 0; n < 8; n++) {
        *reinterpret_cast<float2*>(og + (r0 << 6) + (n << 3) + cb) =
            make_float2(oacc[n][0], oacc[n][1]);
        *reinterpret_cast<float2*>(og + (r1 << 6) + (n << 3) + cb) =
            make_float2(oacc[n][2], oacc[n][3]);
    }
}

extern "C" void kernel_launch(void* const* d_in, const int* in_sizes, int n_in,
                              void* d_out, int out_size) {
    const float* q    = (const float*)d_in[0];
    const float* k    = (const float*)d_in[1];
    const float* v    = (const float*)d_in[2];
    const int*   mask = (const int*)  d_in[3];
    float*       out  = (float*)d_out;

    pack_mask_kernel<<<16, 64>>>(mask);
    cudaFuncSetAttribute(attn64_r15,
                         cudaFuncAttributeMaxDynamicSharedMemorySize, SMEM_BYTES);
    attn64_r15<<<8192, 128, SMEM_BYTES>>>(q, k, v, out);
}

// round 16
// speedup vs baseline: 1.5600x; 1.0082x over previous
#include <cuda_runtime.h>
#include <cuda_fp16.h>
#include <cstdint>

typedef uint32_t u32;
typedef unsigned long long u64;

// smem regions (bytes): fp16 [64x64] tiles, rows 128B, XOR-swizzled 16B granules.
// Pure-fp16 QK and PV (residual passes dropped per calibrated error budget). 24KB.
#define R_QH 0
#define R_KH 8192
#define R_VH 16384
#define SMEM_BYTES 24576

// Packed mask bits: 16 batches x 64 rows, bit c = mask[b][r][c].
__device__ u64 g_mask_bits[16 * 64];

__device__ __forceinline__ u32 smem_u32(const void* p) {
    u32 a;
    asm("{ .reg .u64 t; cvta.to.shared.u64 t, %1; cvt.u32.u64 %0, t; }" : "=r"(a) : "l"(p));
    return a;
}
__device__ __forceinline__ u32 packh(float f0, float f1) {    // lo half=f0, hi half=f1
    u32 r;
    asm("cvt.rn.f16x2.f32 %0, %1, %2;" : "=r"(r) : "f"(f1), "f"(f0));
    return r;
}
__device__ __forceinline__ void ldsm4(u32* r, u32 addr) {
    asm volatile("ldmatrix.sync.aligned.m8n8.x4.shared.b16 {%0,%1,%2,%3}, [%4];"
        : "=r"(r[0]), "=r"(r[1]), "=r"(r[2]), "=r"(r[3]) : "r"(addr));
}
__device__ __forceinline__ void ldsm4t(u32* r, u32 addr) {
    asm volatile("ldmatrix.sync.aligned.m8n8.x4.trans.shared.b16 {%0,%1,%2,%3}, [%4];"
        : "=r"(r[0]), "=r"(r[1]), "=r"(r[2]), "=r"(r[3]) : "r"(addr));
}
__device__ __forceinline__ void mma16816(float* c, const u32* a, const u32* b) {
    asm volatile(
        "mma.sync.aligned.m16n8k16.row.col.f32.f16.f16.f32 "
        "{%0,%1,%2,%3}, {%4,%5,%6,%7}, {%8,%9}, {%0,%1,%2,%3};"
        : "+f"(c[0]), "+f"(c[1]), "+f"(c[2]), "+f"(c[3])
        : "r"(a[0]), "r"(a[1]), "r"(a[2]), "r"(a[3]), "r"(b[0]), "r"(b[1]));
}

// ---- Pre-kernel: pack mask ints into per-row u64 bitmasks (deterministic) ----
__global__ void pack_mask_kernel(const int* __restrict__ mg) {
    const int b = blockIdx.x;                     // 0..15
    const int r = threadIdx.x;                    // 0..63
    const int4* row = reinterpret_cast<const int4*>(mg + b * 4096 + r * 64);
    u64 bits = 0;
    #pragma unroll
    for (int j = 0; j < 16; j++) {
        int4 m = row[j];
        u64 b4 = (m.x != 0 ? 1ull : 0ull) | (m.y != 0 ? 2ull : 0ull)
               | (m.z != 0 ? 4ull : 0ull) | (m.w != 0 ? 8ull : 0ull);
        bits |= b4 << (j << 2);
    }
    g_mask_bits[b * 64 + r] = bits;
}

__global__ void __launch_bounds__(128, 6)
attn64_r16(const float* __restrict__ qg_, const float* __restrict__ kg_,
           const float* __restrict__ vg_, float* __restrict__ og_)
{
    extern __shared__ char smem[];
    const u32 sbase = smem_u32(smem);
    const int tid  = threadIdx.x;
    const int lane = tid & 31;
    const int w    = tid >> 5;                    // warp -> S rows 16w..16w+15

    const int pg = blockIdx.x;                    // one 64x64x64 problem per CTA
    const float* qg = qg_ + (size_t)pg * 4096;
    const float* kg = kg_ + (size_t)pg * 4096;
    const float* vg = vg_ + (size_t)pg * 4096;
    float*       og = og_ + (size_t)pg * 4096;

    // ---- Stage: fp32 -> fp16 hi (Q, K, V), swizzled granule^(row&7) ----
    #pragma unroll
    for (int it = 0; it < 4; it++) {
        int idx = tid + (it << 7);                // 0..511
        int e = idx << 3;                         // 8 source floats
        int r = idx >> 3;                         // row 0..63
        int h = idx & 7;                          // granule 0..7
        int off = (r << 7) + ((h ^ (r & 7)) << 4);
        float4 f0, f1;
        uint4 hq;

        f0 = *reinterpret_cast<const float4*>(qg + e);
        f1 = *reinterpret_cast<const float4*>(qg + e + 4);
        hq.x = packh(f0.x, f0.y); hq.y = packh(f0.z, f0.w);
        hq.z = packh(f1.x, f1.y); hq.w = packh(f1.z, f1.w);
        *reinterpret_cast<uint4*>(smem + R_QH + off) = hq;

        f0 = *reinterpret_cast<const float4*>(kg + e);
        f1 = *reinterpret_cast<const float4*>(kg + e + 4);
        hq.x = packh(f0.x, f0.y); hq.y = packh(f0.z, f0.w);
        hq.z = packh(f1.x, f1.y); hq.w = packh(f1.z, f1.w);
        *reinterpret_cast<uint4*>(smem + R_KH + off) = hq;

        f0 = *reinterpret_cast<const float4*>(vg + e);
        f1 = *reinterpret_cast<const float4*>(vg + e + 4);
        hq.x = packh(f0.x, f0.y); hq.y = packh(f0.z, f0.w);
        hq.z = packh(f1.x, f1.y); hq.w = packh(f1.z, f1.w);
        *reinterpret_cast<uint4*>(smem + R_VH + off) = hq;
    }
    __syncthreads();

    // ---- ldmatrix address templates (validated rounds 9-15) ----
    const int sw      = lane & 7;
    const int a_row   = (w << 4) + (lane & 7) + (((lane >> 3) & 1) << 3);
    const int a_ga    = lane >> 4;                // A order: (r,g)(r8,g)(r,g1)(r8,g1)
    const u32 a_base  = sbase + (u32)(a_row << 7);
    const int tau     = lane >> 3;
    const int kb_radd = ((tau >> 1) << 3) + (lane & 7);  // K: (r,g)(r,g1)(r8,g)(r8,g1)
    const int kb_ga   = tau & 1;
    const int vb_radd = ((tau & 1) << 3) + (lane & 7);   // V: (k,g)(k8,g)(k,g1)(k8,g1)
    const int vb_ga   = tau >> 1;

    // ---- S = Q K^T : pure fp16 (Qh*Kh), 8 n-frags, fp32 accum ----
    float accS[8][4];
    #pragma unroll
    for (int n = 0; n < 8; n++)
        #pragma unroll
        for (int i = 0; i < 4; i++) accS[n][i] = 0.0f;

    #pragma unroll
    for (int kc = 0; kc < 4; kc++) {
        int ag = (kc << 1) + a_ga;
        u32 qh[4];
        ldsm4(qh, a_base + R_QH + ((ag ^ sw) << 4));
        int kg_ = (kc << 1) + kb_ga;
        u32 kh[16];
        #pragma unroll
        for (int np = 0; np < 4; np++) {
            u32 roff = (u32)(((np << 4) + kb_radd) << 7) + (u32)((kg_ ^ sw) << 4);
            ldsm4(&kh[np << 2], sbase + R_KH + roff);
        }
        #pragma unroll
        for (int n = 0; n < 8; n++)
            mma16816(accS[n], qh, &kh[n << 1]);
    }

    // ---- Mask: 2 packed u64 loads ----
    const int r0 = (w << 4) + (lane >> 2);
    const int r1 = r0 + 8;
    const int cb = (lane & 3) << 1;
    const u64* mbase = g_mask_bits + ((pg >> 9) << 6);
    const u64 mb0 = mbase[r0];
    const u64 mb1 = mbase[r1];

    // ---- Softmax IN PLACE in accS (quad shuffles over the 4 col-lanes) ----
    #pragma unroll
    for (int n = 0; n < 8; n++) {
        int c0 = (n << 3) + cb;
        accS[n][0] = ((mb0 >> c0) & 1ull)       ? accS[n][0] * 0.125f : -32768.0f;
        accS[n][1] = ((mb0 >> (c0 + 1)) & 1ull) ? accS[n][1] * 0.125f : -32768.0f;
        accS[n][2] = ((mb1 >> c0) & 1ull)       ? accS[n][2] * 0.125f : -32768.0f;
        accS[n][3] = ((mb1 >> (c0 + 1)) & 1ull) ? accS[n][3] * 0.125f : -32768.0f;
    }
    float mx0 = accS[0][0], mx1 = accS[0][2];
    #pragma unroll
    for (int n = 0; n < 8; n++) {
        mx0 = fmaxf(mx0, fmaxf(accS[n][0], accS[n][1]));
        mx1 = fmaxf(mx1, fmaxf(accS[n][2], accS[n][3]));
    }
    mx0 = fmaxf(mx0, __shfl_xor_sync(0xffffffffu, mx0, 1));
    mx0 = fmaxf(mx0, __shfl_xor_sync(0xffffffffu, mx0, 2));
    mx1 = fmaxf(mx1, __shfl_xor_sync(0xffffffffu, mx1, 1));
    mx1 = fmaxf(mx1, __shfl_xor_sync(0xffffffffu, mx1, 2));
    float s0 = 0.0f, s1 = 0.0f;
    #pragma unroll
    for (int n = 0; n < 8; n++) {
        accS[n][0] = __expf(accS[n][0] - mx0); s0 += accS[n][0];
        accS[n][1] = __expf(accS[n][1] - mx0); s0 += accS[n][1];
        accS[n][2] = __expf(accS[n][2] - mx1); s1 += accS[n][2];
        accS[n][3] = __expf(accS[n][3] - mx1); s1 += accS[n][3];
    }
    s0 += __shfl_xor_sync(0xffffffffu, s0, 1);
    s0 += __shfl_xor_sync(0xffffffffu, s0, 2);
    s1 += __shfl_xor_sync(0xffffffffu, s1, 1);
    s1 += __shfl_xor_sync(0xffffffffu, s1, 2);
    const float i0 = 1.0f / s0, i1 = 1.0f / s1;

    // ---- Pack P hi A-fragments straight from accS ----
    // p(r0, col 8n+cb+{0,1}) = accS[n][0..1], p(r1, ...) = accS[n][2..3].
    // A-frag for kc uses n = 2kc (cols 16kc..16kc+7) and n = 2kc+1 (cols +8..15).
    u32 ph[4][4];
    #pragma unroll
    for (int kc = 0; kc < 4; kc++) {
        ph[kc][0] = packh(accS[2*kc][0]   * i0, accS[2*kc][1]   * i0);
        ph[kc][1] = packh(accS[2*kc][2]   * i1, accS[2*kc][3]   * i1);
        ph[kc][2] = packh(accS[2*kc+1][0] * i0, accS[2*kc+1][1] * i0);
        ph[kc][3] = packh(accS[2*kc+1][2] * i1, accS[2*kc+1][3] * i1);
    }

    // ---- O = P V : single pass Ph*Vh, V frags via ldsm.trans ----
    float oacc[8][4];
    #pragma unroll
    for (int n = 0; n < 8; n++)
        #pragma unroll
        for (int i = 0; i < 4; i++) oacc[n][i] = 0.0f;

    #pragma unroll
    for (int kc = 0; kc < 4; kc++) {
        u32 vh[16];
        #pragma unroll
        for (int np = 0; np < 4; np++) {
            int vgr = (np << 1) + vb_ga;
            u32 roff = (u32)(((kc << 4) + vb_radd) << 7) + (u32)((vgr ^ sw) << 4);
            ldsm4t(&vh[np << 2], sbase + R_VH + roff);
        }
        #pragma unroll
        for (int n = 0; n < 8; n++)
            mma16816(oacc[n], ph[kc], &vh[n << 1]);
    }

    // ---- Direct coalesced-sector stores (32B row segments per lane quartet) ----
    #pragma unroll
    for (int n = 0; n < 8; n++) {
        *reinterpret_cast<float2*>(og + (r0 << 6) + (n << 3) + cb) =
            make_float2(oacc[n][0], oacc[n][1]);
        *reinterpret_cast<float2*>(og + (r1 << 6) + (n << 3) + cb) =
            make_float2(oacc[n][2], oacc[n][3]);
    }
}

extern "C" void kernel_launch(void* const* d_in, const int* in_sizes, int n_in,
                              void* d_out, int out_size) {
    const float* q    = (const float*)d_in[0];
    const float* k    = (const float*)d_in[1];
    const float* v    = (const float*)d_in[2];
    const int*   mask = (const int*)  d_in[3];
    float*       out  = (float*)d_out;

    pack_mask_kernel<<<16, 64>>>(mask);
    cudaFuncSetAttribute(attn64_r16,
                         cudaFuncAttributeMaxDynamicSharedMemorySize, SMEM_BYTES);
    attn64_r16<<<8192, 128, SMEM_BYTES>>>(q, k, v, out);
}

// round 17
// speedup vs baseline: 1.5617x; 1.0011x over previous
#include <cuda_runtime.h>
#include <cuda_fp16.h>
#include <cstdint>

typedef uint32_t u32;
typedef unsigned long long u64;

// smem regions (bytes): fp16 [64x64] tiles, rows 128B, XOR-swizzled 16B granules.
// Pure-fp16 QK and PV (residual passes dropped per calibrated error budget). 24KB.
#define R_QH 0
#define R_KH 8192
#define R_VH 16384
#define SMEM_BYTES 24576

// Packed mask bits: 16 batches x 64 rows, bit c = mask[b][r][c].
__device__ u64 g_mask_bits[16 * 64];

__device__ __forceinline__ u32 smem_u32(const void* p) {
    u32 a;
    asm("{ .reg .u64 t; cvta.to.shared.u64 t, %1; cvt.u32.u64 %0, t; }" : "=r"(a) : "l"(p));
    return a;
}
__device__ __forceinline__ u32 packh(float f0, float f1) {    // lo half=f0, hi half=f1
    u32 r;
    asm("cvt.rn.f16x2.f32 %0, %1, %2;" : "=r"(r) : "f"(f1), "f"(f0));
    return r;
}
__device__ __forceinline__ void ldsm4(u32* r, u32 addr) {
    asm volatile("ldmatrix.sync.aligned.m8n8.x4.shared.b16 {%0,%1,%2,%3}, [%4];"
        : "=r"(r[0]), "=r"(r[1]), "=r"(r[2]), "=r"(r[3]) : "r"(addr));
}
__device__ __forceinline__ void ldsm4t(u32* r, u32 addr) {
    asm volatile("ldmatrix.sync.aligned.m8n8.x4.trans.shared.b16 {%0,%1,%2,%3}, [%4];"
        : "=r"(r[0]), "=r"(r[1]), "=r"(r[2]), "=r"(r[3]) : "r"(addr));
}
__device__ __forceinline__ void mma16816(float* c, const u32* a, const u32* b) {
    asm volatile(
        "mma.sync.aligned.m16n8k16.row.col.f32.f16.f16.f32 "
        "{%0,%1,%2,%3}, {%4,%5,%6,%7}, {%8,%9}, {%0,%1,%2,%3};"
        : "+f"(c[0]), "+f"(c[1]), "+f"(c[2]), "+f"(c[3])
        : "r"(a[0]), "r"(a[1]), "r"(a[2]), "r"(a[3]), "r"(b[0]), "r"(b[1]));
}

// ---- Pre-kernel: pack mask ints into per-row u64 bitmasks.
// 4 threads per row (4x MLP vs the 1-thread/row version), quad shfl-OR combine.
__global__ void pack_mask_kernel(const int* __restrict__ mg) {
    const int b = blockIdx.x;                     // 0..15
    const int t = threadIdx.x;                    // 0..255
    const int r = t >> 2;                         // row 0..63
    const int q = t & 3;                          // quarter 0..3 (cols 16q..16q+15)
    const int4* seg = reinterpret_cast<const int4*>(mg + b * 4096 + r * 64) + (q << 2);
    u64 bits = 0;
    #pragma unroll
    for (int j = 0; j < 4; j++) {
        int4 m = seg[j];
        u64 b4 = (m.x != 0 ? 1ull : 0ull) | (m.y != 0 ? 2ull : 0ull)
               | (m.z != 0 ? 4ull : 0ull) | (m.w != 0 ? 8ull : 0ull);
        bits |= b4 << ((q << 4) + (j << 2));
    }
    bits |= __shfl_xor_sync(0xffffffffu, bits, 1);
    bits |= __shfl_xor_sync(0xffffffffu, bits, 2);
    if (q == 0) g_mask_bits[b * 64 + r] = bits;
}

__global__ void __launch_bounds__(128, 6)
attn64_r17(const float* __restrict__ qg_, const float* __restrict__ kg_,
           const float* __restrict__ vg_, float* __restrict__ og_)
{
    extern __shared__ char smem[];
    const u32 sbase = smem_u32(smem);
    const int tid  = threadIdx.x;
    const int lane = tid & 31;
    const int w    = tid >> 5;                    // warp -> S rows 16w..16w+15

    const int pg = blockIdx.x;                    // one 64x64x64 problem per CTA
    const float* qg = qg_ + (size_t)pg * 4096;
    const float* kg = kg_ + (size_t)pg * 4096;
    const float* vg = vg_ + (size_t)pg * 4096;
    float*       og = og_ + (size_t)pg * 4096;

    // ---- Mask loads issued FIRST: L2 latency hides under staging + QK ----
    const int r0 = (w << 4) + (lane >> 2);
    const int r1 = r0 + 8;
    const int cb = (lane & 3) << 1;
    const u64* mbase = g_mask_bits + ((pg >> 9) << 6);
    const u64 mb0 = mbase[r0];
    const u64 mb1 = mbase[r1];

    // ---- Stage: fp32 -> fp16 hi (Q, K, V), swizzled granule^(row&7) ----
    #pragma unroll
    for (int it = 0; it < 4; it++) {
        int idx = tid + (it << 7);                // 0..511
        int e = idx << 3;                         // 8 source floats
        int r = idx >> 3;                         // row 0..63
        int h = idx & 7;                          // granule 0..7
        int off = (r << 7) + ((h ^ (r & 7)) << 4);
        float4 f0, f1;
        uint4 hq;

        f0 = *reinterpret_cast<const float4*>(qg + e);
        f1 = *reinterpret_cast<const float4*>(qg + e + 4);
        hq.x = packh(f0.x, f0.y); hq.y = packh(f0.z, f0.w);
        hq.z = packh(f1.x, f1.y); hq.w = packh(f1.z, f1.w);
        *reinterpret_cast<uint4*>(smem + R_QH + off) = hq;

        f0 = *reinterpret_cast<const float4*>(kg + e);
        f1 = *reinterpret_cast<const float4*>(kg + e + 4);
        hq.x = packh(f0.x, f0.y); hq.y = packh(f0.z, f0.w);
        hq.z = packh(f1.x, f1.y); hq.w = packh(f1.z, f1.w);
        *reinterpret_cast<uint4*>(smem + R_KH + off) = hq;

        f0 = *reinterpret_cast<const float4*>(vg + e);
        f1 = *reinterpret_cast<const float4*>(vg + e + 4);
        hq.x = packh(f0.x, f0.y); hq.y = packh(f0.z, f0.w);
        hq.z = packh(f1.x, f1.y); hq.w = packh(f1.z, f1.w);
        *reinterpret_cast<uint4*>(smem + R_VH + off) = hq;
    }
    __syncthreads();

    // ---- ldmatrix address templates (validated rounds 9-16) ----
    const int sw      = lane & 7;
    const int a_row   = (w << 4) + (lane & 7) + (((lane >> 3) & 1) << 3);
    const int a_ga    = lane >> 4;                // A order: (r,g)(r8,g)(r,g1)(r8,g1)
    const u32 a_base  = sbase + (u32)(a_row << 7);
    const int tau     = lane >> 3;
    const int kb_radd = ((tau >> 1) << 3) + (lane & 7);  // K: (r,g)(r,g1)(r8,g)(r8,g1)
    const int kb_ga   = tau & 1;
    const int vb_radd = ((tau & 1) << 3) + (lane & 7);   // V: (k,g)(k8,g)(k,g1)(k8,g1)
    const int vb_ga   = tau >> 1;

    // ---- S = Q K^T : pure fp16 (Qh*Kh), 8 n-frags, fp32 accum ----
    float accS[8][4];
    #pragma unroll
    for (int n = 0; n < 8; n++)
        #pragma unroll
        for (int i = 0; i < 4; i++) accS[n][i] = 0.0f;

    #pragma unroll
    for (int kc = 0; kc < 4; kc++) {
        int ag = (kc << 1) + a_ga;
        u32 qh[4];
        ldsm4(qh, a_base + R_QH + ((ag ^ sw) << 4));
        int kg_ = (kc << 1) + kb_ga;
        u32 kh[16];
        #pragma unroll
        for (int np = 0; np < 4; np++) {
            u32 roff = (u32)(((np << 4) + kb_radd) << 7) + (u32)((kg_ ^ sw) << 4);
            ldsm4(&kh[np << 2], sbase + R_KH + roff);
        }
        #pragma unroll
        for (int n = 0; n < 8; n++)
            mma16816(accS[n], qh, &kh[n << 1]);
    }

    // ---- Softmax IN PLACE in accS (quad shuffles over the 4 col-lanes) ----
    #pragma unroll
    for (int n = 0; n < 8; n++) {
        int c0 = (n << 3) + cb;
        accS[n][0] = ((mb0 >> c0) & 1ull)       ? accS[n][0] * 0.125f : -32768.0f;
        accS[n][1] = ((mb0 >> (c0 + 1)) & 1ull) ? accS[n][1] * 0.125f : -32768.0f;
        accS[n][2] = ((mb1 >> c0) & 1ull)       ? accS[n][2] * 0.125f : -32768.0f;
        accS[n][3] = ((mb1 >> (c0 + 1)) & 1ull) ? accS[n][3] * 0.125f : -32768.0f;
    }
    float mx0 = accS[0][0], mx1 = accS[0][2];
    #pragma unroll
    for (int n = 0; n < 8; n++) {
        mx0 = fmaxf(mx0, fmaxf(accS[n][0], accS[n][1]));
        mx1 = fmaxf(mx1, fmaxf(accS[n][2], accS[n][3]));
    }
    mx0 = fmaxf(mx0, __shfl_xor_sync(0xffffffffu, mx0, 1));
    mx0 = fmaxf(mx0, __shfl_xor_sync(0xffffffffu, mx0, 2));
    mx1 = fmaxf(mx1, __shfl_xor_sync(0xffffffffu, mx1, 1));
    mx1 = fmaxf(mx1, __shfl_xor_sync(0xffffffffu, mx1, 2));
    float s0 = 0.0f, s1 = 0.0f;
    #pragma unroll
    for (int n = 0; n < 8; n++) {
        accS[n][0] = __expf(accS[n][0] - mx0); s0 += accS[n][0];
        accS[n][1] = __expf(accS[n][1] - mx0); s0 += accS[n][1];
        accS[n][2] = __expf(accS[n][2] - mx1); s1 += accS[n][2];
        accS[n][3] = __expf(accS[n][3] - mx1); s1 += accS[n][3];
    }
    s0 += __shfl_xor_sync(0xffffffffu, s0, 1);
    s0 += __shfl_xor_sync(0xffffffffu, s0, 2);
    s1 += __shfl_xor_sync(0xffffffffu, s1, 1);
    s1 += __shfl_xor_sync(0xffffffffu, s1, 2);
    const float i0 = 1.0f / s0, i1 = 1.0f / s1;

    // ---- Pack P hi A-fragments straight from accS ----
    u32 ph[4][4];
    #pragma unroll
    for (int kc = 0; kc < 4; kc++) {
        ph[kc][0] = packh(accS[2*kc][0]   * i0, accS[2*kc][1]   * i0);
        ph[kc][1] = packh(accS[2*kc][2]   * i1, accS[2*kc][3]   * i1);
        ph[kc][2] = packh(accS[2*kc+1][0] * i0, accS[2*kc+1][1] * i0);
        ph[kc][3] = packh(accS[2*kc+1][2] * i1, accS[2*kc+1][3] * i1);
    }

    // ---- O = P V : single pass Ph*Vh, V frags via ldsm.trans ----
    float oacc[8][4];
    #pragma unroll
    for (int n = 0; n < 8; n++)
        #pragma unroll
        for (int i = 0; i < 4; i++) oacc[n][i] = 0.0f;

    #pragma unroll
    for (int kc = 0; kc < 4; kc++) {
        u32 vh[16];
        #pragma unroll
        for (int np = 0; np < 4; np++) {
            int vgr = (np << 1) + vb_ga;
            u32 roff = (u32)(((kc << 4) + vb_radd) << 7) + (u32)((vgr ^ sw) << 4);
            ldsm4t(&vh[np << 2], sbase + R_VH + roff);
        }
        #pragma unroll
        for (int n = 0; n < 8; n++)
            mma16816(oacc[n], ph[kc], &vh[n << 1]);
    }

    // ---- Direct coalesced-sector stores (32B row segments per lane quartet) ----
    #pragma unroll
    for (int n = 0; n < 8; n++) {
        *reinterpret_cast<float2*>(og + (r0 << 6) + (n << 3) + cb) =
            make_float2(oacc[n][0], oacc[n][1]);
        *reinterpret_cast<float2*>(og + (r1 << 6) + (n << 3) + cb) =
            make_float2(oacc[n][2], oacc[n][3]);
    }
}

extern "C" void kernel_launch(void* const* d_in, const int* in_sizes, int n_in,
                              void* d_out, int out_size) {
    const float* q    = (const float*)d_in[0];
    const float* k    = (const float*)d_in[1];
    const float* v    = (const float*)d_in[2];
    const int*   mask = (const int*)  d_in[3];
    float*       out  = (float*)d_out;

    pack_mask_kernel<<<16, 256>>>(mask);
    cudaFuncSetAttribute(attn64_r17,
                         cudaFuncAttributeMaxDynamicSharedMemorySize, SMEM_BYTES);
    attn64_r17<<<8192, 128, SMEM_BYTES>>>(q, k, v, out);
}